// round 14
// baseline (speedup 1.0000x reference)
#include <cuda_runtime.h>
#include <cuda_fp16.h>
#include <cstdint>

#define BATCH 32
#define SEQ   2048
#define DC    1024
#define H     512
#define MROWS (BATCH*SEQ)
#define NEG_NUM -10000.0f
#define MAXTILES 2048          // 32 batches x 16 mblocks x 4 nblocks

// ---------------------------------------------------------------------------
// device scratch
// ---------------------------------------------------------------------------
__device__ float g_qbp[4 * BATCH * H];               // qb partials (4 d-chunks)
__device__ float g_part[4 * MROWS];                  // per-nblock score partials
__device__ __align__(128) uint32_t g_Bh[H * DC / 2]; // W1^T fp16 half2, fragment-order
__device__ __align__(128) uint32_t g_Ah[MROWS * DC / 2]; // live ctx rows, fp16, compacted
__device__ int g_rowidx[MROWS];                      // per-batch compacted row indices
__device__ int g_count[BATCH];                       // per-batch masked-in count
__device__ unsigned g_tile_ctr;                      // persistent-gemm queue head
__device__ unsigned g_live_ctr;                      // number of live tiles
__device__ unsigned g_tiles[MAXTILES];               // live tile codes: b<<6|mb<<2|nb

// ---------------------------------------------------------------------------
// helpers
// ---------------------------------------------------------------------------
__device__ __forceinline__ uint32_t pack_f16x2(float lo, float hi) {
    __half2 h = __floats2half2_rn(lo, hi);
    return *(uint32_t*)&h;
}
__device__ __forceinline__ float fast_tanh(float x) {
    float y;
    asm("tanh.approx.f32 %0, %1;" : "=f"(y) : "f"(x));
    return y;
}
__device__ __forceinline__ void mma_f16(float* c, const uint32_t* a, const uint32_t* b) {
    asm volatile(
        "mma.sync.aligned.m16n8k16.row.col.f32.f16.f16.f32 "
        "{%0,%1,%2,%3}, {%4,%5,%6,%7}, {%8,%9}, {%0,%1,%2,%3};"
        : "+f"(c[0]), "+f"(c[1]), "+f"(c[2]), "+f"(c[3])
        : "r"(a[0]), "r"(a[1]), "r"(a[2]), "r"(a[3]),
          "r"(b[0]), "r"(b[1]));
}
__device__ __forceinline__ void cp_async16(uint32_t smem_dst, const void* gsrc) {
    asm volatile("cp.async.cg.shared.global [%0], [%1], 16;"
                 :: "r"(smem_dst), "l"(gsrc));
}
__device__ __forceinline__ void cp_commit() {
    asm volatile("cp.async.commit_group;");
}
template <int N>
__device__ __forceinline__ void cp_wait() {
    asm volatile("cp.async.wait_group %0;" :: "n"(N));
}

// ---------------------------------------------------------------------------
// Kernel 1 (fused):
//  blocks 0..127 : pack W1[:DC] -> g_Bh via smem staging. Block = (kc,nb)
//                  tile [32k x 128n]: coalesced fp32 read -> smem (padded),
//                  fragment-order fp16 write at CONSECUTIVE addresses.
//  blocks 128..383: qb partials, Wq tiled once: block = (hc 0..63 x dc 0..3),
//                  256 active threads = 32 b x 8 h, query slice in smem.
// grid(384), block(1024)
// ---------------------------------------------------------------------------
__global__ void prep_kernel(const float* __restrict__ query,
                            const float* __restrict__ W1,
                            const float* __restrict__ b1) {
    if (blockIdx.x < 128) {
        __shared__ float s_w[32][132];              // padded vs bank conflicts
        int kc = blockIdx.x & 31;
        int nb = blockIdx.x >> 5;
        int tid = threadIdx.x;
        #pragma unroll
        for (int i = tid; i < 32 * 128; i += 1024) {
            int k = i >> 7, n = i & 127;
            s_w[k][n] = W1[(size_t)(kc * 32 + k) * H + nb * 128 + n];
        }
        __syncthreads();
        #pragma unroll
        for (int idl = tid; idl < 2048; idl += 1024) {
            int u    = idl & 1;
            int lane = (idl >> 1) & 31;
            int ks   = (idl >> 6) & 1;
            int nblk = idl >> 7;
            int t = lane & 3, g = lane >> 2;
            int kl = ks * 16 + u * 8 + 2 * t;
            int nl = nblk * 8 + g;
            g_Bh[(size_t)(nb * 32 + kc) * 2048 + idl] =
                pack_f16x2(s_w[kl][nl], s_w[kl + 1][nl]);
        }
        return;
    }
    int qidx = blockIdx.x - 128;                    // 0..255
    int hc = qidx & 63;                             // 8 h's
    int dc = qidx >> 6;                             // 0..3 (256 d's)
    int tid = threadIdx.x;
    if (qidx == 0 && tid == 0) { g_tile_ctr = 0u; g_live_ctr = 0u; }

    __shared__ float sq[32][256];                   // query slice [b][d]
    for (int i = tid; i < 32 * 256; i += 1024) {
        int b = i >> 8, d = i & 255;
        sq[b][d] = query[b * DC + dc * 256 + d];
    }
    __syncthreads();
    if (tid >= 256) return;

    int b  = tid >> 3;
    int h  = hc * 8 + (tid & 7);
    float acc = (dc == 0) ? b1[h] : 0.0f;
    const float* wq = W1 + (size_t)(DC + dc * 256) * H + h;
    #pragma unroll 8
    for (int d = 0; d < 256; d++)
        acc += sq[b][d] * wq[(size_t)d * H];
    g_qbp[(dc * BATCH + b) * H + h] = acc;
}

// ---------------------------------------------------------------------------
// Kernel 2: stable compaction of mask=1 rows per batch; appends live tiles;
// zeroes expected_ctx. grid(32), block(1024)
// ---------------------------------------------------------------------------
__global__ void mask_scan_kernel(const int* __restrict__ mask,
                                 float* __restrict__ out_ec) {
    int b = blockIdx.x;
    int t = threadIdx.x;
    out_ec[b * DC + t] = 0.0f;
    int lane = t & 31, warp = t >> 5;
    int s0 = 2 * t, s1 = 2 * t + 1;
    int v0 = (mask[b * SEQ + s0] != 0) ? 1 : 0;
    int v1 = (mask[b * SEQ + s1] != 0) ? 1 : 0;
    int loc = v0 + v1;

    int x = loc;
    #pragma unroll
    for (int o = 1; o < 32; o <<= 1) {
        int y = __shfl_up_sync(0xffffffffu, x, o);
        if (lane >= o) x += y;
    }
    __shared__ int wsums[32];
    if (lane == 31) wsums[warp] = x;
    __syncthreads();
    if (t < 32) {
        int y = wsums[t];
        #pragma unroll
        for (int o = 1; o < 32; o <<= 1) {
            int z = __shfl_up_sync(0xffffffffu, y, o);
            if (t >= o) y += z;
        }
        wsums[t] = y;
    }
    __syncthreads();
    int base = (warp ? wsums[warp - 1] : 0) + x - loc;   // exclusive prefix
    if (v0) g_rowidx[b * SEQ + base] = s0;
    if (v1) g_rowidx[b * SEQ + base + v0] = s1;
    if (t == 1023) {
        int count = wsums[31];
        g_count[b] = count;
        int nmb = (count + 127) >> 7;                    // live mblocks
        unsigned tb = atomicAdd(&g_live_ctr, (unsigned)(nmb * 4));
        for (int i = 0; i < nmb * 4; i++)
            g_tiles[tb + i] = ((unsigned)b << 6) | ((unsigned)(i >> 2) << 2) | (i & 3);
    }
}

// ---------------------------------------------------------------------------
// Kernel 2b: gather live ctx rows -> compacted fp16 g_Ah. MLP=16: flat index
// over a 16-row chunk, all loads independent and fully unrolled.
// grid(32 /*b*/, 128 /*16-row chunk*/), block(256)
// ---------------------------------------------------------------------------
__global__ __launch_bounds__(256)
void convert_kernel(const float* __restrict__ ctx) {
    int b  = blockIdx.x;
    int c0 = blockIdx.y * 16;
    int count = g_count[b];
    if (c0 >= count) return;
    int tid = threadIdx.x;

    __shared__ int srow[16];
    if (tid < 16) {
        int rr = c0 + tid;
        srow[tid] = g_rowidx[b * SEQ + (rr < count ? rr : count - 1)];
    }
    __syncthreads();

    int nrows = min(16, count - c0);
    const float4* cb = (const float4*)(ctx + (size_t)b * SEQ * DC);
    uint2* ab = (uint2*)g_Ah + ((size_t)b * SEQ + c0) * 256;
    #pragma unroll
    for (int i = 0; i < 16; i++) {
        int idx = i * 256 + tid;
        int rl  = idx >> 8;
        int col = idx & 255;
        if (rl < nrows) {
            float4 v = cb[(size_t)srow[rl] * 256 + col];
            uint2 w;
            w.x = pack_f16x2(v.x, v.y);
            w.y = pack_f16x2(v.z, v.w);
            ab[rl * 256 + col] = w;
        }
    }
}

// ---------------------------------------------------------------------------
// Kernel 3: persistent FP16 mma.sync GEMM over compacted fp16 rows.
// BM=128 BN=128 BK=32, 8 warps (2m x 4n), warp tile 64x32 (m16n8k16 x 32),
// A and B both via cp.async (pre-packed fp16), 4 stages, 2 CTAs/SM.
// grid(304), block(256)
// ---------------------------------------------------------------------------
#define A_WPAD 20                      // words per A row (16 + 4 pad)
#define A_WORDS (128 * A_WPAD)         // 2560 words = 10KB
#define B_WORDS 2048                   // 8KB
#define STAGE_WORDS (A_WORDS + B_WORDS)
#define NSTAGE 4
#define SMEM_DYN (STAGE_WORDS * NSTAGE * 4)

__global__ __launch_bounds__(256, 2)
void gemm_kernel(const float* __restrict__ W2) {
    extern __shared__ uint32_t smem[];
    __shared__ float s_qb[128];
    __shared__ float s_w2[128];
    __shared__ int   s_idx[128];
    __shared__ float s_red[4][128];
    __shared__ unsigned s_tile;

    const int tid  = threadIdx.x;
    const int warp = tid >> 5;
    const int lane = tid & 31;
    const int wm   = warp >> 2;
    const int wn   = warp & 3;
    const int g    = lane >> 2;
    const int t    = lane & 3;

    const unsigned total = g_live_ctr;
    const uint32_t smem_base = (uint32_t)__cvta_generic_to_shared(smem);
    const int aoff = (wm * 64 + g) * A_WPAD + t;
    const int boff = lane * 2;

    // A chunk mapping (constant): chunk idx = tid + j*256; r = idx>>2, c = idx&3
    int ar[2], adst[2];
    #pragma unroll
    for (int j = 0; j < 2; j++) {
        int idxj = tid + j * 256;
        ar[j]   = idxj >> 2;
        adst[j] = (idxj >> 2) * A_WPAD + (idxj & 3) * 4;
    }

    for (;;) {
        __syncthreads();
        if (tid == 0) s_tile = atomicAdd(&g_tile_ctr, 1u);
        __syncthreads();
        const unsigned qidx = s_tile;
        if (qidx >= total) break;
        const unsigned tile = g_tiles[qidx];

        const int nb    = tile & 3;
        const int mb    = (int)((tile >> 2) & 15);
        const int b     = (int)(tile >> 6);
        const int count = g_count[b];
        const int brow0 = mb * 128;

        if (tid < 128) {
            int hq = b * H + nb * 128 + tid;
            s_qb[tid] = g_qbp[hq] + g_qbp[BATCH * H + hq]
                      + g_qbp[2 * BATCH * H + hq] + g_qbp[3 * BATCH * H + hq];
            s_w2[tid] = W2[nb * 128 + tid];
            int rr = brow0 + tid;
            s_idx[tid] = g_rowidx[b * SEQ + (rr < count ? rr : count - 1)];
        }

        const uint32_t* asrc0 = g_Ah + ((size_t)b * SEQ + brow0) * (DC / 2);
        const uint32_t* bsrc0 = g_Bh + (size_t)nb * 32 * B_WORDS;

        auto issue = [&](int kc, int s) {
            uint32_t aBase = smem_base + (uint32_t)(s * STAGE_WORDS) * 4u;
            uint32_t bBase = aBase + A_WORDS * 4u;
            #pragma unroll
            for (int j = 0; j < 2; j++) {
                int idxj = tid + j * 256;
                cp_async16(aBase + (uint32_t)adst[j] * 4u,
                           asrc0 + (size_t)ar[j] * (DC / 2) + kc * 16 + (idxj & 3) * 4);
            }
            const uint32_t* bsrc = bsrc0 + (size_t)kc * B_WORDS;
            cp_async16(bBase + (uint32_t)tid * 16u, bsrc + tid * 4);
            cp_async16(bBase + (uint32_t)(tid + 256) * 16u, bsrc + (tid + 256) * 4);
        };

        float acc[4][4][4];
        #pragma unroll
        for (int mt = 0; mt < 4; mt++)
            #pragma unroll
            for (int nt = 0; nt < 4; nt++)
                #pragma unroll
                for (int j = 0; j < 4; j++)
                    acc[mt][nt][j] = 0.0f;

        issue(0, 0); cp_commit();
        issue(1, 1); cp_commit();
        issue(2, 2); cp_commit();

        for (int kc = 0; kc < 32; kc++) {
            const int s = kc & (NSTAGE - 1);
            cp_wait<NSTAGE - 2>();
            __syncthreads();

            if (kc + NSTAGE - 1 < 32) issue(kc + NSTAGE - 1, (kc + NSTAGE - 1) & (NSTAGE - 1));
            cp_commit();

            const uint32_t* sA = smem + s * STAGE_WORDS;
            const uint32_t* sB = sA + A_WORDS;

            #pragma unroll
            for (int ks = 0; ks < 2; ks++) {
                uint32_t af[4][4];
                #pragma unroll
                for (int mt = 0; mt < 4; mt++) {
                    const uint32_t* base = sA + aoff + mt * 16 * A_WPAD + ks * 8;
                    af[mt][0] = base[0];
                    af[mt][1] = base[8 * A_WPAD];
                    af[mt][2] = base[4];
                    af[mt][3] = base[8 * A_WPAD + 4];
                }
                uint32_t bf[4][2];
                #pragma unroll
                for (int nt = 0; nt < 4; nt++) {
                    int nblk = wn * 4 + nt;
                    const uint2 v = *(const uint2*)(sB + (nblk * 2 + ks) * 64 + boff);
                    bf[nt][0] = v.x;
                    bf[nt][1] = v.y;
                }
                #pragma unroll
                for (int mt = 0; mt < 4; mt++)
                    #pragma unroll
                    for (int nt = 0; nt < 4; nt++)
                        mma_f16(acc[mt][nt], af[mt], bf[nt]);
            }
        }
        cp_wait<0>();

        // --- epilogue: per-warp tanh partials, cross-wn smem reduce, write ---
        float w2v[4][2], qv[4][2];
        #pragma unroll
        for (int nt = 0; nt < 4; nt++)
            #pragma unroll
            for (int j = 0; j < 2; j++) {
                int hl = wn * 32 + nt * 8 + 2 * t + j;
                w2v[nt][j] = s_w2[hl];
                qv[nt][j]  = s_qb[hl];
            }

        #pragma unroll
        for (int mt = 0; mt < 4; mt++) {
            int rl = wm * 64 + mt * 16 + g;
            float p0 = 0.0f, p1 = 0.0f;
            #pragma unroll
            for (int nt = 0; nt < 4; nt++) {
                #pragma unroll
                for (int j = 0; j < 2; j++) {
                    p0 += fast_tanh(acc[mt][nt][j]     + qv[nt][j]) * w2v[nt][j];
                    p1 += fast_tanh(acc[mt][nt][2 + j] + qv[nt][j]) * w2v[nt][j];
                }
            }
            p0 += __shfl_xor_sync(0xffffffffu, p0, 1);
            p0 += __shfl_xor_sync(0xffffffffu, p0, 2);
            p1 += __shfl_xor_sync(0xffffffffu, p1, 1);
            p1 += __shfl_xor_sync(0xffffffffu, p1, 2);
            if (t == 0) {
                s_red[wn][rl]     = p0;
                s_red[wn][rl + 8] = p1;
            }
        }
        __syncthreads();
        if (tid < 128 && brow0 + tid < count) {
            float val = s_red[0][tid] + s_red[1][tid] + s_red[2][tid] + s_red[3][tid];
            g_part[(size_t)nb * MROWS + b * SEQ + s_idx[tid]] = val;
        }
    }
}

// ---------------------------------------------------------------------------
// Kernel 4: masked softmax per batch row (sums 4 n-block partials).
// grid(32), block(1024)
// ---------------------------------------------------------------------------
__global__ void softmax_kernel(const int* __restrict__ mask,
                               const float* __restrict__ b2,
                               float* __restrict__ p_out) {
    int b   = blockIdx.x;
    int tid = threadIdx.x;
    __shared__ float red[32];

    const float bias = b2[0];
    int i0 = b * SEQ + tid;
    int i1 = i0 + 1024;
    float s0 = NEG_NUM, s1 = NEG_NUM;
    if (mask[i0] != 0)
        s0 = g_part[i0] + g_part[MROWS + i0] + g_part[2*MROWS + i0] + g_part[3*MROWS + i0] + bias;
    if (mask[i1] != 0)
        s1 = g_part[i1] + g_part[MROWS + i1] + g_part[2*MROWS + i1] + g_part[3*MROWS + i1] + bias;

    float m = fmaxf(s0, s1);
    #pragma unroll
    for (int o = 16; o > 0; o >>= 1)
        m = fmaxf(m, __shfl_xor_sync(0xffffffffu, m, o));
    if ((tid & 31) == 0) red[tid >> 5] = m;
    __syncthreads();
    if (tid < 32) {
        float v = red[tid];
        #pragma unroll
        for (int o = 16; o > 0; o >>= 1)
            v = fmaxf(v, __shfl_xor_sync(0xffffffffu, v, o));
        red[tid] = v;
    }
    __syncthreads();
    m = red[0];
    __syncthreads();

    float e0 = __expf(s0 - m);
    float e1 = __expf(s1 - m);
    float sm = e0 + e1;
    #pragma unroll
    for (int o = 16; o > 0; o >>= 1)
        sm += __shfl_xor_sync(0xffffffffu, sm, o);
    if ((tid & 31) == 0) red[tid >> 5] = sm;
    __syncthreads();
    if (tid < 32) {
        float v = red[tid];
        #pragma unroll
        for (int o = 16; o > 0; o >>= 1)
            v += __shfl_xor_sync(0xffffffffu, v, o);
        red[tid] = v;
    }
    __syncthreads();
    float inv = 1.0f / red[0];

    p_out[i0] = e0 * inv;
    p_out[i1] = e1 * inv;
}

// ---------------------------------------------------------------------------
// Kernel 5: expected_ctx[b][d] = sum over LIVE rows of p * ctx, reading the
// COMPACTED fp16 g_Ah sequentially (no gather, half the bytes).
// grid(32 /*b*/, 16 /*compacted chunk 128*/), block(256), atomic accumulate.
// ---------------------------------------------------------------------------
__global__ __launch_bounds__(256)
void wsum_kernel(const float* __restrict__ p,
                 float* __restrict__ out_ec) {
    int b   = blockIdx.x;
    int r0  = blockIdx.y * 128;
    int count = g_count[b];
    if (r0 >= count) return;
    int tid = threadIdx.x;                // covers d = tid*4 .. tid*4+3
    int n   = min(128, count - r0);

    __shared__ float sw[128];
    if (tid < 128) {
        int rr = r0 + tid;
        sw[tid] = (rr < count) ? p[b * SEQ + g_rowidx[b * SEQ + rr]] : 0.0f;
    }
    __syncthreads();

    const uint2* abase = (const uint2*)(g_Ah + ((size_t)b * SEQ + r0) * (DC / 2)) + tid;
    float4 acc = make_float4(0.f, 0.f, 0.f, 0.f);
    #pragma unroll 4
    for (int s = 0; s < n; s++) {
        float w = sw[s];
        uint2 v = abase[(size_t)s * 256];
        float2 f0 = __half22float2(*(const __half2*)&v.x);
        float2 f1 = __half22float2(*(const __half2*)&v.y);
        acc.x += w * f0.x;
        acc.y += w * f0.y;
        acc.z += w * f1.x;
        acc.w += w * f1.y;
    }
    float* o = out_ec + b * DC + tid * 4;
    atomicAdd(o + 0, acc.x);
    atomicAdd(o + 1, acc.y);
    atomicAdd(o + 2, acc.z);
    atomicAdd(o + 3, acc.w);
}

// ---------------------------------------------------------------------------
// launch
// ---------------------------------------------------------------------------
extern "C" void kernel_launch(void* const* d_in, const int* in_sizes, int n_in,
                              void* d_out, int out_size) {
    const float* ctx   = (const float*)d_in[0];
    const float* query = (const float*)d_in[1];
    const float* W1    = (const float*)d_in[2];
    const float* b1    = (const float*)d_in[3];
    const float* W2    = (const float*)d_in[4];
    const float* b2    = (const float*)d_in[5];
    const int*   mask  = (const int*)d_in[6];

    float* out    = (float*)d_out;
    float* out_ec = out;
    float* out_p  = out + BATCH * DC;

    static bool attr_set = false;
    if (!attr_set) {
        cudaFuncSetAttribute(gemm_kernel,
                             cudaFuncAttributeMaxDynamicSharedMemorySize, SMEM_DYN);
        attr_set = true;
    }

    prep_kernel<<<384, 1024>>>(query, W1, b1);
    mask_scan_kernel<<<BATCH, 1024>>>(mask, out_ec);
    convert_kernel<<<dim3(BATCH, 128), 256>>>(ctx);
    gemm_kernel<<<304, 256, SMEM_DYN>>>(W2);
    softmax_kernel<<<BATCH, 1024>>>(mask, b2, out_p);
    wsum_kernel<<<dim3(BATCH, 16), 256>>>(out_p, out_ec);
}

// round 15
// speedup vs baseline: 1.2103x; 1.2103x over previous
#include <cuda_runtime.h>
#include <cuda_fp16.h>
#include <cstdint>

#define BATCH 32
#define SEQ   2048
#define DC    1024
#define H     512
#define MROWS (BATCH*SEQ)
#define NEG_NUM -10000.0f
#define NTILES 2048            // 32 batches x 16 mblocks x 4 nblocks

// ---------------------------------------------------------------------------
// device scratch
// ---------------------------------------------------------------------------
__device__ float g_qbp[4 * BATCH * H];               // qb partials (4 d-chunks)
__device__ float g_part[4 * MROWS];                  // per-nblock score partials
__device__ __align__(128) uint32_t g_Bh[H * DC / 2]; // W1^T fp16 half2, fragment-order
__device__ __align__(128) uint32_t g_Ah[MROWS * DC / 2]; // live ctx rows, fp16, compacted
__device__ int g_rowidx[MROWS];                      // per-batch compacted row indices
__device__ int g_count[BATCH];                       // per-batch masked-in count
__device__ unsigned g_tile_ctr;                      // persistent-gemm queue head
                                                     // (reset by wsum each replay)

// ---------------------------------------------------------------------------
// helpers
// ---------------------------------------------------------------------------
__device__ __forceinline__ uint32_t pack_f16x2(float lo, float hi) {
    __half2 h = __floats2half2_rn(lo, hi);
    return *(uint32_t*)&h;
}
__device__ __forceinline__ float fast_tanh(float x) {
    float y;
    asm("tanh.approx.f32 %0, %1;" : "=f"(y) : "f"(x));
    return y;
}
__device__ __forceinline__ void mma_f16(float* c, const uint32_t* a, const uint32_t* b) {
    asm volatile(
        "mma.sync.aligned.m16n8k16.row.col.f32.f16.f16.f32 "
        "{%0,%1,%2,%3}, {%4,%5,%6,%7}, {%8,%9}, {%0,%1,%2,%3};"
        : "+f"(c[0]), "+f"(c[1]), "+f"(c[2]), "+f"(c[3])
        : "r"(a[0]), "r"(a[1]), "r"(a[2]), "r"(a[3]),
          "r"(b[0]), "r"(b[1]));
}
__device__ __forceinline__ void cp_async16(uint32_t smem_dst, const void* gsrc) {
    asm volatile("cp.async.cg.shared.global [%0], [%1], 16;"
                 :: "r"(smem_dst), "l"(gsrc));
}
__device__ __forceinline__ void cp_commit() {
    asm volatile("cp.async.commit_group;");
}
template <int N>
__device__ __forceinline__ void cp_wait() {
    asm volatile("cp.async.wait_group %0;" :: "n"(N));
}

// ---------------------------------------------------------------------------
// Kernel 1 (fused, side stream):
//  blocks 0..255  : pack W1[:DC] -> g_Bh (fp16 fragment order), 1024 thr.
//  blocks 256..511: qb partials, Wq tiled once: block = (hc 0..63 x dc 0..3),
//                   256 active threads = 32 b x 8 h, query slice in smem.
// grid(512), block(1024)
// ---------------------------------------------------------------------------
__global__ void prep_kernel(const float* __restrict__ query,
                            const float* __restrict__ W1,
                            const float* __restrict__ b1) {
    if (blockIdx.x < 256) {
        int id = blockIdx.x * 1024 + threadIdx.x;   // 0..262143
        int u    = id & 1;
        int lane = (id >> 1) & 31;
        int ks   = (id >> 6) & 1;
        int nblk = (id >> 7) & 15;
        int kc   = (id >> 11) & 31;
        int nb   = id >> 16;
        int t = lane & 3, g = lane >> 2;
        int k = kc * 32 + ks * 16 + u * 8 + 2 * t;
        int n = nb * 128 + nblk * 8 + g;
        float lo = W1[(size_t)k * H + n];
        float hi = W1[(size_t)(k + 1) * H + n];
        g_Bh[id] = pack_f16x2(lo, hi);
        return;
    }
    int qidx = blockIdx.x - 256;                    // 0..255
    int hc = qidx & 63;                             // 8 h's
    int dc = qidx >> 6;                             // 0..3 (256 d's)
    int tid = threadIdx.x;

    __shared__ float sq[32][256];                   // query slice [b][d]
    for (int i = tid; i < 32 * 256; i += 1024) {
        int b = i >> 8, d = i & 255;
        sq[b][d] = query[b * DC + dc * 256 + d];
    }
    __syncthreads();
    if (tid >= 256) return;

    int b  = tid >> 3;
    int h  = hc * 8 + (tid & 7);
    float acc = (dc == 0) ? b1[h] : 0.0f;
    const float* wq = W1 + (size_t)(DC + dc * 256) * H + h;
    #pragma unroll 8
    for (int d = 0; d < 256; d++)
        acc += sq[b][d] * wq[(size_t)d * H];
    g_qbp[(dc * BATCH + b) * H + h] = acc;
}

// ---------------------------------------------------------------------------
// Kernel 2: stable compaction of mask=1 rows per batch; zeroes expected_ctx.
// grid(32), block(1024)
// ---------------------------------------------------------------------------
__global__ void mask_scan_kernel(const int* __restrict__ mask,
                                 float* __restrict__ out_ec) {
    int b = blockIdx.x;
    int t = threadIdx.x;
    out_ec[b * DC + t] = 0.0f;
    int lane = t & 31, warp = t >> 5;
    int s0 = 2 * t, s1 = 2 * t + 1;
    int v0 = (mask[b * SEQ + s0] != 0) ? 1 : 0;
    int v1 = (mask[b * SEQ + s1] != 0) ? 1 : 0;
    int loc = v0 + v1;

    int x = loc;
    #pragma unroll
    for (int o = 1; o < 32; o <<= 1) {
        int y = __shfl_up_sync(0xffffffffu, x, o);
        if (lane >= o) x += y;
    }
    __shared__ int wsums[32];
    if (lane == 31) wsums[warp] = x;
    __syncthreads();
    if (t < 32) {
        int y = wsums[t];
        #pragma unroll
        for (int o = 1; o < 32; o <<= 1) {
            int z = __shfl_up_sync(0xffffffffu, y, o);
            if (t >= o) y += z;
        }
        wsums[t] = y;
    }
    __syncthreads();
    int base = (warp ? wsums[warp - 1] : 0) + x - loc;   // exclusive prefix
    if (v0) g_rowidx[b * SEQ + base] = s0;
    if (v1) g_rowidx[b * SEQ + base + v0] = s1;
    if (t == 1023) g_count[b] = wsums[31];
}

// ---------------------------------------------------------------------------
// Kernel 2b: gather live ctx rows -> compacted fp16 g_Ah.
// grid(32 /*b*/, 16 /*row-chunk 128*/), block(256)
// ---------------------------------------------------------------------------
__global__ __launch_bounds__(256)
void convert_kernel(const float* __restrict__ ctx) {
    int b  = blockIdx.x;
    int r0 = blockIdx.y * 128;
    int count = g_count[b];
    if (r0 >= count) return;
    int tid = threadIdx.x;
    int rend = min(r0 + 128, count);
    #pragma unroll 2
    for (int r = r0; r < rend; r++) {
        int row = g_rowidx[b * SEQ + r];
        const float4* src = (const float4*)(ctx + ((size_t)b * SEQ + row) * DC) + tid;
        uint2* dst = (uint2*)(g_Ah + ((size_t)b * SEQ + r) * (DC / 2)) + tid;
        float4 v = *src;
        uint2 w;
        w.x = pack_f16x2(v.x, v.y);
        w.y = pack_f16x2(v.z, v.w);
        *dst = w;
    }
}

// ---------------------------------------------------------------------------
// Kernel 3: persistent FP16 mma.sync GEMM over compacted fp16 rows.
// BM=128 BN=128 BK=32, 8 warps (2m x 4n), warp tile 64x32 (m16n8k16 x 32),
// A and B both via cp.async (pre-packed fp16), 4 stages, 2 CTAs/SM.
// All 2048 tile codes popped from atomic queue; dead tiles continue fast.
// grid(304), block(256)
// ---------------------------------------------------------------------------
#define A_WPAD 20                      // words per A row (16 + 4 pad)
#define A_WORDS (128 * A_WPAD)         // 2560 words = 10KB
#define B_WORDS 2048                   // 8KB
#define STAGE_WORDS (A_WORDS + B_WORDS)
#define NSTAGE 4
#define SMEM_DYN (STAGE_WORDS * NSTAGE * 4)

__global__ __launch_bounds__(256, 2)
void gemm_kernel(const float* __restrict__ W2) {
    extern __shared__ uint32_t smem[];
    __shared__ float s_qb[128];
    __shared__ float s_w2[128];
    __shared__ int   s_idx[128];
    __shared__ float s_red[4][128];
    __shared__ unsigned s_tile;

    const int tid  = threadIdx.x;
    const int warp = tid >> 5;
    const int lane = tid & 31;
    const int wm   = warp >> 2;
    const int wn   = warp & 3;
    const int g    = lane >> 2;
    const int t    = lane & 3;

    const uint32_t smem_base = (uint32_t)__cvta_generic_to_shared(smem);
    const int aoff = (wm * 64 + g) * A_WPAD + t;
    const int boff = lane * 2;

    // A chunk mapping (constant): chunk idx = tid + j*256; r = idx>>2, c = idx&3
    int ar[2], adst[2];
    #pragma unroll
    for (int j = 0; j < 2; j++) {
        int idxj = tid + j * 256;
        ar[j]   = idxj >> 2;
        adst[j] = (idxj >> 2) * A_WPAD + (idxj & 3) * 4;
    }

    for (;;) {
        __syncthreads();                 // all threads done with prev tile's smem
        if (tid == 0) s_tile = atomicAdd(&g_tile_ctr, 1u);
        __syncthreads();                 // publish s_tile
        const unsigned tile = s_tile;
        if (tile >= NTILES) break;

        const int nb    = (int)(tile & 3);
        const int mb    = (int)((tile >> 2) & 15);
        const int b     = (int)(tile >> 6);
        const int count = g_count[b];
        const int brow0 = mb * 128;
        if (brow0 >= count) continue;    // dead tile: cheap pop

        if (tid < 128) {
            int hq = b * H + nb * 128 + tid;
            s_qb[tid] = g_qbp[hq] + g_qbp[BATCH * H + hq]
                      + g_qbp[2 * BATCH * H + hq] + g_qbp[3 * BATCH * H + hq];
            s_w2[tid] = W2[nb * 128 + tid];
            int rr = brow0 + tid;
            s_idx[tid] = g_rowidx[b * SEQ + (rr < count ? rr : count - 1)];
        }

        const uint32_t* asrc0 = g_Ah + ((size_t)b * SEQ + brow0) * (DC / 2);
        const uint32_t* bsrc0 = g_Bh + (size_t)nb * 32 * B_WORDS;

        auto issue = [&](int kc, int s) {
            uint32_t aBase = smem_base + (uint32_t)(s * STAGE_WORDS) * 4u;
            uint32_t bBase = aBase + A_WORDS * 4u;
            #pragma unroll
            for (int j = 0; j < 2; j++) {
                int idxj = tid + j * 256;
                cp_async16(aBase + (uint32_t)adst[j] * 4u,
                           asrc0 + (size_t)ar[j] * (DC / 2) + kc * 16 + (idxj & 3) * 4);
            }
            const uint32_t* bsrc = bsrc0 + (size_t)kc * B_WORDS;
            cp_async16(bBase + (uint32_t)tid * 16u, bsrc + tid * 4);
            cp_async16(bBase + (uint32_t)(tid + 256) * 16u, bsrc + (tid + 256) * 4);
        };

        float acc[4][4][4];
        #pragma unroll
        for (int mt = 0; mt < 4; mt++)
            #pragma unroll
            for (int nt = 0; nt < 4; nt++)
                #pragma unroll
                for (int j = 0; j < 4; j++)
                    acc[mt][nt][j] = 0.0f;

        issue(0, 0); cp_commit();
        issue(1, 1); cp_commit();
        issue(2, 2); cp_commit();

        for (int kc = 0; kc < 32; kc++) {
            const int s = kc & (NSTAGE - 1);
            cp_wait<NSTAGE - 2>();
            __syncthreads();

            if (kc + NSTAGE - 1 < 32) issue(kc + NSTAGE - 1, (kc + NSTAGE - 1) & (NSTAGE - 1));
            cp_commit();

            const uint32_t* sA = smem + s * STAGE_WORDS;
            const uint32_t* sB = sA + A_WORDS;

            #pragma unroll
            for (int ks = 0; ks < 2; ks++) {
                uint32_t af[4][4];
                #pragma unroll
                for (int mt = 0; mt < 4; mt++) {
                    const uint32_t* base = sA + aoff + mt * 16 * A_WPAD + ks * 8;
                    af[mt][0] = base[0];
                    af[mt][1] = base[8 * A_WPAD];
                    af[mt][2] = base[4];
                    af[mt][3] = base[8 * A_WPAD + 4];
                }
                uint32_t bf[4][2];
                #pragma unroll
                for (int nt = 0; nt < 4; nt++) {
                    int nblk = wn * 4 + nt;
                    const uint2 v = *(const uint2*)(sB + (nblk * 2 + ks) * 64 + boff);
                    bf[nt][0] = v.x;
                    bf[nt][1] = v.y;
                }
                #pragma unroll
                for (int mt = 0; mt < 4; mt++)
                    #pragma unroll
                    for (int nt = 0; nt < 4; nt++)
                        mma_f16(acc[mt][nt], af[mt], bf[nt]);
            }
        }
        cp_wait<0>();

        // --- epilogue: per-warp tanh partials, cross-wn smem reduce, write ---
        float w2v[4][2], qv[4][2];
        #pragma unroll
        for (int nt = 0; nt < 4; nt++)
            #pragma unroll
            for (int j = 0; j < 2; j++) {
                int hl = wn * 32 + nt * 8 + 2 * t + j;
                w2v[nt][j] = s_w2[hl];
                qv[nt][j]  = s_qb[hl];
            }

        #pragma unroll
        for (int mt = 0; mt < 4; mt++) {
            int rl = wm * 64 + mt * 16 + g;
            float p0 = 0.0f, p1 = 0.0f;
            #pragma unroll
            for (int nt = 0; nt < 4; nt++) {
                #pragma unroll
                for (int j = 0; j < 2; j++) {
                    p0 += fast_tanh(acc[mt][nt][j]     + qv[nt][j]) * w2v[nt][j];
                    p1 += fast_tanh(acc[mt][nt][2 + j] + qv[nt][j]) * w2v[nt][j];
                }
            }
            p0 += __shfl_xor_sync(0xffffffffu, p0, 1);
            p0 += __shfl_xor_sync(0xffffffffu, p0, 2);
            p1 += __shfl_xor_sync(0xffffffffu, p1, 1);
            p1 += __shfl_xor_sync(0xffffffffu, p1, 2);
            if (t == 0) {
                s_red[wn][rl]     = p0;
                s_red[wn][rl + 8] = p1;
            }
        }
        __syncthreads();
        if (tid < 128 && brow0 + tid < count) {
            float val = s_red[0][tid] + s_red[1][tid] + s_red[2][tid] + s_red[3][tid];
            g_part[(size_t)nb * MROWS + b * SEQ + s_idx[tid]] = val;
        }
    }
}

// ---------------------------------------------------------------------------
// Kernel 4: masked softmax per batch row (sums 4 n-block partials).
// grid(32), block(1024)
// ---------------------------------------------------------------------------
__global__ void softmax_kernel(const int* __restrict__ mask,
                               const float* __restrict__ b2,
                               float* __restrict__ p_out) {
    int b   = blockIdx.x;
    int tid = threadIdx.x;
    __shared__ float red[32];

    const float bias = b2[0];
    int i0 = b * SEQ + tid;
    int i1 = i0 + 1024;
    float s0 = NEG_NUM, s1 = NEG_NUM;
    if (mask[i0] != 0)
        s0 = g_part[i0] + g_part[MROWS + i0] + g_part[2*MROWS + i0] + g_part[3*MROWS + i0] + bias;
    if (mask[i1] != 0)
        s1 = g_part[i1] + g_part[MROWS + i1] + g_part[2*MROWS + i1] + g_part[3*MROWS + i1] + bias;

    float m = fmaxf(s0, s1);
    #pragma unroll
    for (int o = 16; o > 0; o >>= 1)
        m = fmaxf(m, __shfl_xor_sync(0xffffffffu, m, o));
    if ((tid & 31) == 0) red[tid >> 5] = m;
    __syncthreads();
    if (tid < 32) {
        float v = red[tid];
        #pragma unroll
        for (int o = 16; o > 0; o >>= 1)
            v = fmaxf(v, __shfl_xor_sync(0xffffffffu, v, o));
        red[tid] = v;
    }
    __syncthreads();
    m = red[0];
    __syncthreads();

    float e0 = __expf(s0 - m);
    float e1 = __expf(s1 - m);
    float sm = e0 + e1;
    #pragma unroll
    for (int o = 16; o > 0; o >>= 1)
        sm += __shfl_xor_sync(0xffffffffu, sm, o);
    if ((tid & 31) == 0) red[tid >> 5] = sm;
    __syncthreads();
    if (tid < 32) {
        float v = red[tid];
        #pragma unroll
        for (int o = 16; o > 0; o >>= 1)
            v += __shfl_xor_sync(0xffffffffu, v, o);
        red[tid] = v;
    }
    __syncthreads();
    float inv = 1.0f / red[0];

    p_out[i0] = e0 * inv;
    p_out[i1] = e1 * inv;
}

// ---------------------------------------------------------------------------
// Kernel 5: expected_ctx[b][d] = sum over LIVE rows of p * ctx, reading the
// COMPACTED fp16 g_Ah sequentially. Also resets the gemm tile queue for the
// NEXT graph replay (graph-serialized: wsum_N completes before gemm_{N+1}).
// grid(32 /*b*/, 16 /*compacted chunk 128*/), block(256), atomic accumulate.
// ---------------------------------------------------------------------------
__global__ __launch_bounds__(256)
void wsum_kernel(const float* __restrict__ p,
                 float* __restrict__ out_ec) {
    int b   = blockIdx.x;
    int r0  = blockIdx.y * 128;
    int tid = threadIdx.x;                // covers d = tid*4 .. tid*4+3
    if (b == 0 && blockIdx.y == 0 && tid == 0) g_tile_ctr = 0u;  // next replay
    int count = g_count[b];
    if (r0 >= count) return;
    int n   = min(128, count - r0);

    __shared__ float sw[128];
    if (tid < 128) {
        int rr = r0 + tid;
        sw[tid] = (rr < count) ? p[b * SEQ + g_rowidx[b * SEQ + rr]] : 0.0f;
    }
    __syncthreads();

    const uint2* abase = (const uint2*)(g_Ah + ((size_t)b * SEQ + r0) * (DC / 2)) + tid;
    float4 acc = make_float4(0.f, 0.f, 0.f, 0.f);
    #pragma unroll 4
    for (int s = 0; s < n; s++) {
        float w = sw[s];
        uint2 v = abase[(size_t)s * 256];
        float2 f0 = __half22float2(*(const __half2*)&v.x);
        float2 f1 = __half22float2(*(const __half2*)&v.y);
        acc.x += w * f0.x;
        acc.y += w * f0.y;
        acc.z += w * f1.x;
        acc.w += w * f1.y;
    }
    float* o = out_ec + b * DC + tid * 4;
    atomicAdd(o + 0, acc.x);
    atomicAdd(o + 1, acc.y);
    atomicAdd(o + 2, acc.z);
    atomicAdd(o + 3, acc.w);
}

// ---------------------------------------------------------------------------
// launch: prep forked onto a side stream, overlapping mask_scan + convert.
// ---------------------------------------------------------------------------
extern "C" void kernel_launch(void* const* d_in, const int* in_sizes, int n_in,
                              void* d_out, int out_size) {
    const float* ctx   = (const float*)d_in[0];
    const float* query = (const float*)d_in[1];
    const float* W1    = (const float*)d_in[2];
    const float* b1    = (const float*)d_in[3];
    const float* W2    = (const float*)d_in[4];
    const float* b2    = (const float*)d_in[5];
    const int*   mask  = (const int*)d_in[6];

    float* out    = (float*)d_out;
    float* out_ec = out;
    float* out_p  = out + BATCH * DC;

    static cudaStream_t s_side = nullptr;
    static cudaEvent_t  ev_fork = nullptr, ev_join = nullptr;
    if (s_side == nullptr) {
        cudaStreamCreateWithFlags(&s_side, cudaStreamNonBlocking);
        cudaEventCreateWithFlags(&ev_fork, cudaEventDisableTiming);
        cudaEventCreateWithFlags(&ev_join, cudaEventDisableTiming);
        cudaFuncSetAttribute(gemm_kernel,
                             cudaFuncAttributeMaxDynamicSharedMemorySize, SMEM_DYN);
    }

    // fork: prep runs concurrently with mask_scan + convert
    cudaEventRecord(ev_fork, 0);
    cudaStreamWaitEvent(s_side, ev_fork, 0);
    prep_kernel<<<512, 1024, 0, s_side>>>(query, W1, b1);
    cudaEventRecord(ev_join, s_side);

    mask_scan_kernel<<<BATCH, 1024>>>(mask, out_ec);
    convert_kernel<<<dim3(BATCH, 16), 256>>>(ctx);

    // join before gemm (needs g_Bh + g_qbp from prep)
    cudaStreamWaitEvent(0, ev_join, 0);
    gemm_kernel<<<304, 256, SMEM_DYN>>>(W2);
    softmax_kernel<<<BATCH, 1024>>>(mask, b2, out_p);
    wsum_kernel<<<dim3(BATCH, 16), 256>>>(out_p, out_ec);
}